// round 13
// baseline (speedup 1.0000x reference)
#include <cuda_runtime.h>
#include <cstdint>
#include <math.h>

#define BATCH 1000
#define NUE   4
#define KC    500
#define MC    500
#define NC    1000
#define NSYM  250
#define NEDGE 2000
#define NINFO 1500
#define NROW  (BATCH*NSYM)   // 250000
#define COLS  (BATCH*NUE)    // 4000
#define NGRP  125            // codeword groups of 32

// ---------------- scratch (static device allocations only) ----------------
__device__ uint8_t  g_sym[NROW*NUE];
__device__ float2   g_points[16];
__device__ float    g_Lch[BATCH*NC*NUE];      // [b][n][ue], 16MB
__device__ uint16_t g_pos[NEDGE];             // edge e -> check-major slot (sorted layout)
__device__ uint16_t g_ck[NEDGE];              // slot -> info row k (for parity XOR)
__device__ uint32_t g_sd[MC];                 // per sorted-rank: start | (deg<<16)
__device__ float    g_no, g_wsc;

// ---------------- packed f32x2 helpers (bit-identical per lane) ----------------
__device__ __forceinline__ float2 f2add(float2 a, float2 b){
  float2 r;
  asm("{\n\t.reg .b64 A,B,R;\n\t"
      "mov.b64 A,{%2,%3};\n\tmov.b64 B,{%4,%5};\n\t"
      "add.rn.f32x2 R,A,B;\n\tmov.b64 {%0,%1},R;\n\t}"
      : "=f"(r.x),"=f"(r.y) : "f"(a.x),"f"(a.y),"f"(b.x),"f"(b.y));
  return r;
}
__device__ __forceinline__ float2 f2mul(float2 a, float2 b){
  float2 r;
  asm("{\n\t.reg .b64 A,B,R;\n\t"
      "mov.b64 A,{%2,%3};\n\tmov.b64 B,{%4,%5};\n\t"
      "mul.rn.f32x2 R,A,B;\n\tmov.b64 {%0,%1},R;\n\t}"
      : "=f"(r.x),"=f"(r.y) : "f"(a.x),"f"(a.y),"f"(b.x),"f"(b.y));
  return r;
}
__device__ __forceinline__ float2 f2fma(float2 a, float2 b, float2 c){
  float2 r;
  asm("{\n\t.reg .b64 A,B,C,R;\n\t"
      "mov.b64 A,{%2,%3};\n\tmov.b64 B,{%4,%5};\n\tmov.b64 C,{%6,%7};\n\t"
      "fma.rn.f32x2 R,A,B,C;\n\tmov.b64 {%0,%1},R;\n\t}"
      : "=f"(r.x),"=f"(r.y) : "f"(a.x),"f"(a.y),"f"(b.x),"f"(b.y),"f"(c.x),"f"(c.y));
  return r;
}
__device__ __forceinline__ float2 f2c(float k){ return make_float2(k,k); }

// ---------------- setup: points + degree-sorted check-major CSR (1 block) -------
__global__ void k_setup(const int* __restrict__ cn, const float* __restrict__ ebno) {
  __shared__ int      s_cn[NINFO];
  __shared__ uint16_t s_cnt[MC];     // info-degree per check
  __shared__ uint16_t s_rank[MC];    // check -> sorted rank
  __shared__ uint16_t s_start[MC];   // check -> slot start (in sorted layout)
  int tid = threadIdx.x;
  if (tid == 0) {
    float no = 1.0f / (powf(10.0f, ebno[0] / 10.0f) * 4.0f * 0.5f);
    g_no = no;
    g_wsc = sqrtf(no / 2.0f);
  }
  if (tid < 16) {
    int b0=(tid>>3)&1, b1=(tid>>2)&1, b2=(tid>>1)&1, b3=tid&1;
    double re = (double)((1-2*b0)*(2-(1-2*b2)));
    double im = (double)((1-2*b1)*(2-(1-2*b3)));
    double s = sqrt(10.0);
    g_points[tid] = make_float2((float)(re/s), (float)(im/s));
  }
  for (int i = tid; i < NINFO; i += blockDim.x) s_cn[i] = cn[i];
  __syncthreads();
  for (int ch = tid; ch < MC; ch += blockDim.x) {
    int c = 0;
    for (int e = 0; e < NINFO; e++) c += (s_cn[e] == ch);
    s_cnt[ch] = (uint16_t)c;
  }
  __syncthreads();
  // stable counting sort by total degree (cnt+1), then assign ranks + starts
  if (tid == 0) {
    int rank = 0, acc = 0;
    for (int dg = 0; dg < 64; dg++) {
      for (int ch = 0; ch < MC; ch++) {
        if ((int)s_cnt[ch] + 1 == dg) {
          s_rank[ch]  = (uint16_t)rank;
          s_start[ch] = (uint16_t)acc;
          acc += dg;
          rank++;
        }
      }
    }
  }
  __syncthreads();
  for (int ch = tid; ch < MC; ch += blockDim.x) {
    int p = s_start[ch];
    for (int e = 0; e < NINFO; e++)
      if (s_cn[e] == ch) { g_pos[e] = (uint16_t)p; g_ck[p] = (uint16_t)(e/3); p++; }
    g_pos[NINFO + ch] = (uint16_t)p;   // identity edge last (largest e)
    g_sd[s_rank[ch]] = (uint32_t)s_start[ch] | ((uint32_t)(s_cnt[ch] + 1) << 16);
  }
}

// ---------------- encode: bf out + ballot transpose + parity XOR + symbols ----
__global__ void __launch_bounds__(256) k_encode(const int* __restrict__ b,
                                                float* __restrict__ out) {
  __shared__ uint32_t s_bT[512];
  __shared__ uint32_t s_parT[512];
  int g = blockIdx.x, tid = threadIdx.x;
  int base_bu = g * 32;
  const int* bblk = b + base_bu * KC;
  {
    const int4* src = reinterpret_cast<const int4*>(bblk);
    float4* dst = reinterpret_cast<float4*>(out + base_bu * KC);
    for (int i = tid; i < (32*KC)/4; i += 256) {
      int4 v = src[i];
      dst[i] = make_float4((float)v.x, (float)v.y, (float)v.z, (float)v.w);
    }
  }
  {
    int w = tid >> 5, l = tid & 31;
    int ks = (w * KC) >> 3, ke = ((w + 1) * KC) >> 3;
    const int* rb = bblk + l * KC;
    for (int k = ks; k < ke; k++) {
      unsigned word = __ballot_sync(0xffffffffu, rb[k] != 0);
      if (l == 0) s_bT[k] = word;
    }
  }
  __syncthreads();
  // parity via sorted-rank g_sd (rank order is irrelevant for parity math)
  for (int m = tid; m < MC; m += 256) {
    uint32_t sd = g_sd[m];
    int st = (int)(sd & 0xffffu);
    int ninfo = (int)(sd >> 16) - 1;
    uint32_t acc = 0;
    for (int j = 0; j < ninfo; j++) acc ^= s_bT[g_ck[st + j]];
    // identity slot index st+ninfo corresponds to check id = g_pos lookup; but
    // parity bit position m must be the CHECK ID. Recover it from identity edge:
    // slots are laid out per check; the check id owning this run is found via
    // g_ck? Instead store parity at check id using identity-edge reverse map:
    // identity edge for check ch sits at slot start+ninfo and g_pos[NINFO+ch]
    // points there. We need ch for this rank. Encode ch in upper bits of g_ck
    // of the identity slot: set below in setup? Simpler: recompute via search
    // is too slow; use the fact that g_ck[st..st+ninfo-1] are info rows, and
    // the identity slot g_ck was never written. We instead write parity to
    // s_parT indexed by check id stored in g_ck[identity slot].
    s_parT[g_ck[st + ninfo]] = acc;
  }
  __syncthreads();
  for (int idx = tid; idx < 8*NSYM; idx += 256) {
    int bb_l = idx / NSYM, s = idx - bb_l * NSYM;
    int bb = (base_bu >> 2) + bb_l;
    uchar4 sy;
    uint8_t* sp = reinterpret_cast<uint8_t*>(&sy);
    #pragma unroll
    for (int u = 0; u < 4; u++) {
      int l = bb_l * 4 + u;
      int v = 0;
      #pragma unroll
      for (int q = 0; q < 4; q++) {
        int n = 4*s + q;
        uint32_t word = (n < KC) ? s_bT[n] : s_parT[n - KC];
        v = (v << 1) | (int)((word >> l) & 1u);
      }
      sp[u] = (uint8_t)v;
    }
    *reinterpret_cast<uchar4*>(g_sym + (bb*NSYM + s)*4) = sy;
  }
}

// identity-slot check-id fixup (runs in setup grid slot; tiny)
__global__ void k_fixid() {
  int ch = blockIdx.x*blockDim.x + threadIdx.x;
  if (ch < MC) g_ck[g_pos[NINFO + ch]] = (uint16_t)ch;
}

// ---------------- LMMSE + demap ----------------
struct cpx { float r, i; };
__device__ __forceinline__ cpx cadd(cpx a, cpx b){ cpx c; c.r=a.r+b.r; c.i=a.i+b.i; return c; }
__device__ __forceinline__ cpx csub(cpx a, cpx b){ cpx c; c.r=a.r-b.r; c.i=a.i-b.i; return c; }
__device__ __forceinline__ cpx cmul(cpx a, cpx b){ cpx c; c.r=a.r*b.r - a.i*b.i; c.i=a.r*b.i + a.i*b.r; return c; }
__device__ __forceinline__ cpx cmulc(cpx a, cpx b){ cpx c; c.r=a.r*b.r + a.i*b.i; c.i=a.i*b.r - a.r*b.i; return c; }
__device__ __forceinline__ cpx cdiv(cpx a, cpx b){
  float d = b.r*b.r + b.i*b.i;
  cpx c; c.r = (a.r*b.r + a.i*b.i)/d; c.i = (a.i*b.r - a.r*b.i)/d; return c;
}

__global__ void __launch_bounds__(128) k_lmmse(
    const float* __restrict__ hre, const float* __restrict__ him,
    const float* __restrict__ nre, const float* __restrict__ nim)
{
  __shared__ float2 s_h[16*128];   // [elem][tid], per-thread private slots
  __shared__ float2 s_pts[16];
  int tid = threadIdx.x;
  if (tid < 16) s_pts[tid] = g_points[tid];
  __syncthreads();
  int r = blockIdx.x*128 + tid;
  if (r >= NROW) return;
  float no = g_no;
  float wsc = g_wsc;
  const float SQ2 = 1.41421356237309515f;

  {
    const float4* hre4 = reinterpret_cast<const float4*>(hre + r*16);
    const float4* him4 = reinterpret_cast<const float4*>(him + r*16);
    #pragma unroll
    for (int i=0;i<4;i++){
      float4 a = hre4[i], c = him4[i];
      s_h[(i*4+0)*128+tid] = make_float2(a.x/SQ2, c.x/SQ2);
      s_h[(i*4+1)*128+tid] = make_float2(a.y/SQ2, c.y/SQ2);
      s_h[(i*4+2)*128+tid] = make_float2(a.z/SQ2, c.z/SQ2);
      s_h[(i*4+3)*128+tid] = make_float2(a.w/SQ2, c.w/SQ2);
    }
  }

  const uchar4 sy = *reinterpret_cast<const uchar4*>(g_sym + r*4);
  cpx x[4];
  { float2 p;
    p = g_points[sy.x]; x[0].r=p.x; x[0].i=p.y;
    p = g_points[sy.y]; x[1].r=p.x; x[1].i=p.y;
    p = g_points[sy.z]; x[2].r=p.x; x[2].i=p.y;
    p = g_points[sy.w]; x[3].r=p.x; x[3].i=p.y; }

  cpx B[4][5];
  #pragma unroll
  for (int i=0;i<4;i++)
    #pragma unroll
    for (int j=0;j<4;j++){
      float2 v = s_h[(i*4+j)*128+tid];
      B[i][1+j].r = v.x; B[i][1+j].i = v.y;
    }
  #pragma unroll
  for (int i=0;i<4;i++){
    cpx acc; acc.r=0.f; acc.i=0.f;
    #pragma unroll
    for (int j=0;j<4;j++) acc = cadd(acc, cmul(B[i][1+j], x[j]));
    acc.r += nre[r*4+i]*wsc;
    acc.i += nim[r*4+i]*wsc;
    B[i][0] = acc;
  }
  cpx A[4][4];
  #pragma unroll
  for (int i=0;i<4;i++)
    #pragma unroll
    for (int k=0;k<4;k++){
      cpx acc; acc.r=0.f; acc.i=0.f;
      #pragma unroll
      for (int j=0;j<4;j++) acc = cadd(acc, cmulc(B[i][1+j], B[k][1+j]));
      if (i==k) acc.r += no;
      A[i][k] = acc;
    }

  // LU with partial pivoting (cabs1, bubble-swap keeps static indexing)
  #pragma unroll
  for (int k=0;k<4;k++){
    #pragma unroll
    for (int i=k+1;i<4;i++){
      float vk = fabsf(A[k][k].r)+fabsf(A[k][k].i);
      float vi = fabsf(A[i][k].r)+fabsf(A[i][k].i);
      if (vi > vk){
        #pragma unroll
        for (int j=0;j<4;j++){ cpx tmp=A[k][j]; A[k][j]=A[i][j]; A[i][j]=tmp; }
        #pragma unroll
        for (int j=0;j<5;j++){ cpx tmp=B[k][j]; B[k][j]=B[i][j]; B[i][j]=tmp; }
      }
    }
    #pragma unroll
    for (int i=k+1;i<4;i++){
      cpx l = cdiv(A[i][k], A[k][k]);
      #pragma unroll
      for (int j=k+1;j<4;j++) A[i][j] = csub(A[i][j], cmul(l, A[k][j]));
      #pragma unroll
      for (int j=0;j<5;j++) B[i][j] = csub(B[i][j], cmul(l, B[k][j]));
    }
  }
  #pragma unroll
  for (int k=3;k>=0;k--){
    #pragma unroll
    for (int j=0;j<5;j++){
      cpx s = B[k][j];
      #pragma unroll
      for (int m=k+1;m<4;m++) s = csub(s, cmul(A[k][m], B[m][j]));
      B[k][j] = cdiv(s, A[k][k]);
    }
  }

  int bb = r / NSYM, s = r - bb*NSYM;
  float Lout[16];
  #pragma unroll
  for (int j=0;j<4;j++){
    cpx hj[4];
    #pragma unroll
    for (int i=0;i<4;i++){
      float2 v = s_h[(i*4+j)*128+tid];
      hj[i].r = v.x; hj[i].i = v.y;
    }
    cpx xr; xr.r=0.f; xr.i=0.f;
    float dj = 0.f;
    #pragma unroll
    for (int i=0;i<4;i++) xr = cadd(xr, cmulc(B[i][0], hj[i]));
    #pragma unroll
    for (int i=0;i<4;i++){ cpx t = cmulc(B[i][1+j], hj[i]); dj += t.r; }
    float xhr = xr.r / dj, xhi = xr.i / dj;
    float nv = fmaxf(1.0f/dj - 1.0f, 1e-12f);
    float m0[4] = {-1e30f,-1e30f,-1e30f,-1e30f};
    float m1[4] = {-1e30f,-1e30f,-1e30f,-1e30f};
    #pragma unroll
    for (int p=0;p<16;p++){
      float2 pt = s_pts[p];
      float dr = xhr - pt.x;
      float di = xhi - pt.y;
      float am = sqrtf(dr*dr + di*di);
      float met = -(am*am)/nv;
      #pragma unroll
      for (int q=0;q<4;q++){
        if ((p >> (3-q)) & 1) m1[q] = fmaxf(m1[q], met);
        else                  m0[q] = fmaxf(m0[q], met);
      }
    }
    #pragma unroll
    for (int q=0;q<4;q++) Lout[4*q + j] = m0[q] - m1[q];
  }
  float4* dst = reinterpret_cast<float4*>(g_Lch + bb*(NC*NUE) + 16*s);
  const float4* src = reinterpret_cast<const float4*>(Lout);
  dst[0]=src[0]; dst[1]=src[1]; dst[2]=src[2]; dst[3]=src[3];
}

// ---------------- LDPC decoder ----------------
__device__ __forceinline__ float eps_clamp(float t){
  float m = fmaxf(fabsf(t), 1e-7f);
  return __int_as_float((__float_as_int(t) & 0x80000000) | __float_as_int(m));
}
__device__ __forceinline__ float2 v2c2(float2 mv){
  float2 arg = f2mul(mv, f2c(0.5f));
  float axx = fabsf(arg.x), axy = fabsf(arg.y);
  float2 xc;
  xc.x = fminf(fmaxf(arg.x,-7.90531110763549805f),7.90531110763549805f);
  xc.y = fminf(fmaxf(arg.y,-7.90531110763549805f),7.90531110763549805f);
  float2 x2 = f2mul(xc,xc);
  float2 p = f2c(-2.76076847742355e-16f);
  p = f2fma(p,x2,f2c(2.00018790482477e-13f));
  p = f2fma(p,x2,f2c(-8.60467152213735e-11f));
  p = f2fma(p,x2,f2c(5.12229709037114e-08f));
  p = f2fma(p,x2,f2c(1.48572235717979e-05f));
  p = f2fma(p,x2,f2c(6.37261928875436e-04f));
  p = f2fma(p,x2,f2c(4.89352455891786e-03f));
  p = f2mul(p,xc);
  float2 q = f2c(1.19825839466702e-06f);
  q = f2fma(q,x2,f2c(1.18534705686654e-04f));
  q = f2fma(q,x2,f2c(2.26843463243900e-03f));
  q = f2fma(q,x2,f2c(4.89352518554385e-03f));
  float2 t;
  t.x = p.x/q.x; t.y = p.y/q.y;
  t.x = (axx < 0.0004f) ? arg.x : t.x;
  t.y = (axy < 0.0004f) ? arg.y : t.y;
  t.x = eps_clamp(t.x);
  t.y = eps_clamp(t.y);
  return t;
}
__device__ __forceinline__ float c2v_msg(float prod, float t){
  float ra = prod / t;
  ra = fminf(fmaxf(ra, -0.999999f), 0.999999f);
  float at = 0.5f*(log1pf(ra) - log1pf(-ra));
  return 2.0f*at;
}

__global__ void __launch_bounds__(512) k_decode(float* __restrict__ out){
  __shared__ float4 s_msg[NEDGE];   // 32000 B, check-major slots x 4 codewords
  int bb = blockIdx.x, tid = threadIdx.x;
  const float4* Lg = reinterpret_cast<const float4*>(g_Lch + bb*(NC*NUE));

  float4 Lv, Lp;
  int p0=0, p1=0, p2=0, pid=0;
  int start=0, deg=0;
  bool act = (tid < 500);
  if (act){
    int v = tid;
    Lv = Lg[v];
    Lp = Lg[KC + v];
    p0 = g_pos[3*v]; p1 = g_pos[3*v+1]; p2 = g_pos[3*v+2];
    pid = g_pos[NINFO + v];
    uint32_t sd = g_sd[tid];          // degree-sorted rank -> uniform warp degree
    start = (int)(sd & 0xffffu); deg = (int)(sd >> 16);
  }
  for (int i=tid;i<NEDGE;i+=512) s_msg[i] = make_float4(0.f,0.f,0.f,0.f);
  __syncthreads();

  for (int it=0; it<5; it++){
    // ---- variable nodes (packed pairs xy / zw) ----
    if (act){
      float4 c0 = s_msg[p0], c1 = s_msg[p1], c2 = s_msg[p2];
      float2 c0a = make_float2(c0.x,c0.y), c0b = make_float2(c0.z,c0.w);
      float2 c1a = make_float2(c1.x,c1.y), c1b = make_float2(c1.z,c1.w);
      float2 c2a = make_float2(c2.x,c2.y), c2b = make_float2(c2.z,c2.w);
      float2 La  = make_float2(Lv.x,Lv.y), Lb = make_float2(Lv.z,Lv.w);
      float2 vta = f2add(f2add(f2add(La,c0a),c1a),c2a);
      float2 vtb = f2add(f2add(f2add(Lb,c0b),c1b),c2b);
      float2 n0a = v2c2(make_float2(vta.x-c0a.x, vta.y-c0a.y));
      float2 n0b = v2c2(make_float2(vtb.x-c0b.x, vtb.y-c0b.y));
      float2 n1a = v2c2(make_float2(vta.x-c1a.x, vta.y-c1a.y));
      float2 n1b = v2c2(make_float2(vtb.x-c1b.x, vtb.y-c1b.y));
      float2 n2a = v2c2(make_float2(vta.x-c2a.x, vta.y-c2a.y));
      float2 n2b = v2c2(make_float2(vtb.x-c2b.x, vtb.y-c2b.y));
      s_msg[p0] = make_float4(n0a.x,n0a.y,n0b.x,n0b.y);
      s_msg[p1] = make_float4(n1a.x,n1a.y,n1b.x,n1b.y);
      s_msg[p2] = make_float4(n2a.x,n2a.y,n2b.x,n2b.y);
      float4 cp = s_msg[pid];
      float2 cpa = make_float2(cp.x,cp.y), cpb = make_float2(cp.z,cp.w);
      float2 Lpa = make_float2(Lp.x,Lp.y), Lpb = make_float2(Lp.z,Lp.w);
      float2 ta = f2add(Lpa,cpa);
      float2 tb = f2add(Lpb,cpb);
      float2 npa = v2c2(make_float2(ta.x-cpa.x, ta.y-cpa.y));
      float2 npb = v2c2(make_float2(tb.x-cpb.x, tb.y-cpb.y));
      s_msg[pid] = make_float4(npa.x,npa.y,npb.x,npb.y);
    }
    __syncthreads();
    // ---- check nodes (uniform degree per warp thanks to sorted ranks) ----
    if (act){
      int st = start, dg = deg;
      float2 pa = f2c(1.f), pb = f2c(1.f);
      for (int d=0; d<dg; d++){
        float4 t = s_msg[st+d];
        pa = f2mul(pa, make_float2(t.x,t.y));
        pb = f2mul(pb, make_float2(t.z,t.w));
      }
      for (int d=0; d<dg; d++){
        float4 t = s_msg[st+d];
        float4 o;
        o.x = c2v_msg(pa.x, t.x);
        o.y = c2v_msg(pa.y, t.y);
        o.z = c2v_msg(pb.x, t.z);
        o.w = c2v_msg(pb.y, t.w);
        s_msg[st+d] = o;
      }
    }
    __syncthreads();
  }

  float* bh = out + COLS*KC;
  if (act){
    int v = tid;
    float4 c0 = s_msg[p0], c1 = s_msg[p1], c2 = s_msg[p2];
    float vx = ((Lv.x + c0.x) + c1.x) + c2.x;
    float vy = ((Lv.y + c0.y) + c1.y) + c2.y;
    float vz = ((Lv.z + c0.z) + c1.z) + c2.z;
    float vw = ((Lv.w + c0.w) + c1.w) + c2.w;
    bh[(bb*4+0)*KC + v] = (vx < 0.f) ? 1.0f : 0.0f;
    bh[(bb*4+1)*KC + v] = (vy < 0.f) ? 1.0f : 0.0f;
    bh[(bb*4+2)*KC + v] = (vz < 0.f) ? 1.0f : 0.0f;
    bh[(bb*4+3)*KC + v] = (vw < 0.f) ? 1.0f : 0.0f;
  }
}

// ---------------- entry ----------------
extern "C" void kernel_launch(void* const* d_in, const int* in_sizes, int n_in,
                              void* d_out, int out_size)
{
  (void)in_sizes; (void)out_size;
  int off = (n_in >= 10) ? 1 : 0;
  const float* ebno = (const float*)d_in[off+0];
  const int*   b    = (const int*)  d_in[off+1];
  const int*   cn   = (const int*)  d_in[off+3];
  const float* hre  = (const float*)d_in[off+5];
  const float* him  = (const float*)d_in[off+6];
  const float* nre  = (const float*)d_in[off+7];
  const float* nim  = (const float*)d_in[off+8];
  float* out = (float*)d_out;

  k_setup<<<1, 512>>>(cn, ebno);
  k_fixid<<<2, 256>>>();
  k_encode<<<NGRP, 256>>>(b, out);
  k_lmmse<<<(NROW + 127)/128, 128>>>(hre, him, nre, nim);
  k_decode<<<BATCH, 512>>>(out);
}

// round 17
// speedup vs baseline: 3.4637x; 3.4637x over previous
#include <cuda_runtime.h>
#include <cstdint>
#include <math.h>

#define BATCH 1000
#define NUE   4
#define KC    500
#define MC    500
#define NC    1000
#define NSYM  250
#define NEDGE 2000
#define NINFO 1500
#define NROW  (BATCH*NSYM)   // 250000
#define COLS  (BATCH*NUE)    // 4000
#define NGRP  125            // codeword groups of 32
#define NSLOT 2500           // padded slot budget (<= 2000 edges + 500 pad)

// ---------------- scratch (static device allocations only) ----------------
__device__ uint8_t  g_sym[NROW*NUE];
__device__ float2   g_points[16];
__device__ float    g_Lch[BATCH*NC*NUE];      // [b][n][ue], 16MB
__device__ uint16_t g_pos[NEDGE];             // edge e -> padded sorted slot
__device__ uint16_t g_ck[NSLOT];              // slot -> info row k / (identity: check id)
__device__ uint32_t g_sd[MC];                 // per sorted-rank: start | (deg<<16)
__device__ float    g_no, g_wsc;

// ---------------- packed f32x2 helpers (bit-identical per lane) ----------------
__device__ __forceinline__ float2 f2add(float2 a, float2 b){
  float2 r;
  asm("{\n\t.reg .b64 A,B,R;\n\t"
      "mov.b64 A,{%2,%3};\n\tmov.b64 B,{%4,%5};\n\t"
      "add.rn.f32x2 R,A,B;\n\tmov.b64 {%0,%1},R;\n\t}"
      : "=f"(r.x),"=f"(r.y) : "f"(a.x),"f"(a.y),"f"(b.x),"f"(b.y));
  return r;
}
__device__ __forceinline__ float2 f2mul(float2 a, float2 b){
  float2 r;
  asm("{\n\t.reg .b64 A,B,R;\n\t"
      "mov.b64 A,{%2,%3};\n\tmov.b64 B,{%4,%5};\n\t"
      "mul.rn.f32x2 R,A,B;\n\tmov.b64 {%0,%1},R;\n\t}"
      : "=f"(r.x),"=f"(r.y) : "f"(a.x),"f"(a.y),"f"(b.x),"f"(b.y));
  return r;
}
__device__ __forceinline__ float2 f2fma(float2 a, float2 b, float2 c){
  float2 r;
  asm("{\n\t.reg .b64 A,B,C,R;\n\t"
      "mov.b64 A,{%2,%3};\n\tmov.b64 B,{%4,%5};\n\tmov.b64 C,{%6,%7};\n\t"
      "fma.rn.f32x2 R,A,B,C;\n\tmov.b64 {%0,%1},R;\n\t}"
      : "=f"(r.x),"=f"(r.y) : "f"(a.x),"f"(a.y),"f"(b.x),"f"(b.y),"f"(c.x),"f"(c.y));
  return r;
}
__device__ __forceinline__ float2 f2c(float k){ return make_float2(k,k); }

// ---------------- setup: points + degree-sorted padded CSR (1 block) ----------
__global__ void k_setup(const int* __restrict__ cn, const float* __restrict__ ebno) {
  __shared__ int      s_cn[NINFO];
  __shared__ uint16_t s_cnt[MC];     // info-degree per check
  __shared__ uint16_t s_rank[MC];    // check -> sorted rank
  __shared__ uint16_t s_start[MC];   // check -> padded slot start (sorted layout)
  int tid = threadIdx.x;
  if (tid == 0) {
    float no = 1.0f / (powf(10.0f, ebno[0] / 10.0f) * 4.0f * 0.5f);
    g_no = no;
    g_wsc = sqrtf(no / 2.0f);
  }
  if (tid < 16) {
    int b0=(tid>>3)&1, b1=(tid>>2)&1, b2=(tid>>1)&1, b3=tid&1;
    double re = (double)((1-2*b0)*(2-(1-2*b2)));
    double im = (double)((1-2*b1)*(2-(1-2*b3)));
    double s = sqrt(10.0);
    g_points[tid] = make_float2((float)(re/s), (float)(im/s));
  }
  for (int i = tid; i < NINFO; i += blockDim.x) s_cn[i] = cn[i];
  __syncthreads();
  for (int ch = tid; ch < MC; ch += blockDim.x) {
    int c = 0;
    for (int e = 0; e < NINFO; e++) c += (s_cn[e] == ch);
    s_cnt[ch] = (uint16_t)c;
  }
  __syncthreads();
  // parallel stable rank + padded-start: lexicographic (deg, ch) order.
  // pad(d) = d + !(d&1) -> odd stride in float4 units (<=2-way bank conflicts)
  for (int ch = tid; ch < MC; ch += blockDim.x) {
    int degc = (int)s_cnt[ch] + 1;
    int rank = 0, startv = 0;
    for (int c2 = 0; c2 < MC; c2++) {
      int d2 = (int)s_cnt[c2] + 1;
      bool earlier = (d2 < degc) || (d2 == degc && c2 < ch);
      if (earlier) { rank++; startv += d2 + ((d2 & 1) ^ 1); }
    }
    s_rank[ch]  = (uint16_t)rank;
    s_start[ch] = (uint16_t)startv;
  }
  __syncthreads();
  for (int ch = tid; ch < MC; ch += blockDim.x) {
    int p = s_start[ch];
    for (int e = 0; e < NINFO; e++)
      if (s_cn[e] == ch) { g_pos[e] = (uint16_t)p; g_ck[p] = (uint16_t)(e/3); p++; }
    g_pos[NINFO + ch] = (uint16_t)p;          // identity edge last (largest e)
    g_ck[p] = (uint16_t)ch;                   // identity slot stores check id
    g_sd[s_rank[ch]] = (uint32_t)s_start[ch] | ((uint32_t)(s_cnt[ch] + 1) << 16);
  }
}

// ---------------- encode: bf out + ballot transpose + parity XOR + symbols ----
__global__ void __launch_bounds__(256) k_encode(const int* __restrict__ b,
                                                float* __restrict__ out) {
  __shared__ uint32_t s_bT[512];
  __shared__ uint32_t s_parT[512];
  int g = blockIdx.x, tid = threadIdx.x;
  int base_bu = g * 32;
  const int* bblk = b + base_bu * KC;
  {
    const int4* src = reinterpret_cast<const int4*>(bblk);
    float4* dst = reinterpret_cast<float4*>(out + base_bu * KC);
    for (int i = tid; i < (32*KC)/4; i += 256) {
      int4 v = src[i];
      dst[i] = make_float4((float)v.x, (float)v.y, (float)v.z, (float)v.w);
    }
  }
  {
    int w = tid >> 5, l = tid & 31;
    int ks = (w * KC) >> 3, ke = ((w + 1) * KC) >> 3;
    const int* rb = bblk + l * KC;
    for (int k = ks; k < ke; k++) {
      unsigned word = __ballot_sync(0xffffffffu, rb[k] != 0);
      if (l == 0) s_bT[k] = word;
    }
  }
  __syncthreads();
  // parity via sorted-rank g_sd; parity bit position = check id from identity slot
  for (int m = tid; m < MC; m += 256) {
    uint32_t sd = g_sd[m];
    int st = (int)(sd & 0xffffu);
    int ninfo = (int)(sd >> 16) - 1;
    uint32_t acc = 0;
    for (int j = 0; j < ninfo; j++) acc ^= s_bT[g_ck[st + j]];
    s_parT[g_ck[st + ninfo]] = acc;
  }
  __syncthreads();
  for (int idx = tid; idx < 8*NSYM; idx += 256) {
    int bb_l = idx / NSYM, s = idx - bb_l * NSYM;
    int bb = (base_bu >> 2) + bb_l;
    uchar4 sy;
    uint8_t* sp = reinterpret_cast<uint8_t*>(&sy);
    #pragma unroll
    for (int u = 0; u < 4; u++) {
      int l = bb_l * 4 + u;
      int v = 0;
      #pragma unroll
      for (int q = 0; q < 4; q++) {
        int n = 4*s + q;
        uint32_t word = (n < KC) ? s_bT[n] : s_parT[n - KC];
        v = (v << 1) | (int)((word >> l) & 1u);
      }
      sp[u] = (uint8_t)v;
    }
    *reinterpret_cast<uchar4*>(g_sym + (bb*NSYM + s)*4) = sy;
  }
}

// ---------------- LMMSE + demap ----------------
struct cpx { float r, i; };
__device__ __forceinline__ cpx cadd(cpx a, cpx b){ cpx c; c.r=a.r+b.r; c.i=a.i+b.i; return c; }
__device__ __forceinline__ cpx csub(cpx a, cpx b){ cpx c; c.r=a.r-b.r; c.i=a.i-b.i; return c; }
__device__ __forceinline__ cpx cmul(cpx a, cpx b){ cpx c; c.r=a.r*b.r - a.i*b.i; c.i=a.r*b.i + a.i*b.r; return c; }
__device__ __forceinline__ cpx cmulc(cpx a, cpx b){ cpx c; c.r=a.r*b.r + a.i*b.i; c.i=a.i*b.r - a.r*b.i; return c; }
__device__ __forceinline__ cpx cdiv(cpx a, cpx b){
  float d = b.r*b.r + b.i*b.i;
  cpx c; c.r = (a.r*b.r + a.i*b.i)/d; c.i = (a.i*b.r - a.r*b.i)/d; return c;
}

__global__ void __launch_bounds__(128) k_lmmse(
    const float* __restrict__ hre, const float* __restrict__ him,
    const float* __restrict__ nre, const float* __restrict__ nim)
{
  __shared__ float2 s_h[16*128];   // [elem][tid], per-thread private slots
  __shared__ float2 s_pts[16];
  int tid = threadIdx.x;
  if (tid < 16) s_pts[tid] = g_points[tid];
  __syncthreads();
  int r = blockIdx.x*128 + tid;
  if (r >= NROW) return;
  float no = g_no;
  float wsc = g_wsc;
  const float SQ2 = 1.41421356237309515f;

  {
    const float4* hre4 = reinterpret_cast<const float4*>(hre + r*16);
    const float4* him4 = reinterpret_cast<const float4*>(him + r*16);
    #pragma unroll
    for (int i=0;i<4;i++){
      float4 a = hre4[i], c = him4[i];
      s_h[(i*4+0)*128+tid] = make_float2(a.x/SQ2, c.x/SQ2);
      s_h[(i*4+1)*128+tid] = make_float2(a.y/SQ2, c.y/SQ2);
      s_h[(i*4+2)*128+tid] = make_float2(a.z/SQ2, c.z/SQ2);
      s_h[(i*4+3)*128+tid] = make_float2(a.w/SQ2, c.w/SQ2);
    }
  }

  const uchar4 sy = *reinterpret_cast<const uchar4*>(g_sym + r*4);
  cpx x[4];
  { float2 p;
    p = g_points[sy.x]; x[0].r=p.x; x[0].i=p.y;
    p = g_points[sy.y]; x[1].r=p.x; x[1].i=p.y;
    p = g_points[sy.z]; x[2].r=p.x; x[2].i=p.y;
    p = g_points[sy.w]; x[3].r=p.x; x[3].i=p.y; }

  cpx B[4][5];
  #pragma unroll
  for (int i=0;i<4;i++)
    #pragma unroll
    for (int j=0;j<4;j++){
      float2 v = s_h[(i*4+j)*128+tid];
      B[i][1+j].r = v.x; B[i][1+j].i = v.y;
    }
  #pragma unroll
  for (int i=0;i<4;i++){
    cpx acc; acc.r=0.f; acc.i=0.f;
    #pragma unroll
    for (int j=0;j<4;j++) acc = cadd(acc, cmul(B[i][1+j], x[j]));
    acc.r += nre[r*4+i]*wsc;
    acc.i += nim[r*4+i]*wsc;
    B[i][0] = acc;
  }
  cpx A[4][4];
  #pragma unroll
  for (int i=0;i<4;i++)
    #pragma unroll
    for (int k=0;k<4;k++){
      cpx acc; acc.r=0.f; acc.i=0.f;
      #pragma unroll
      for (int j=0;j<4;j++) acc = cadd(acc, cmulc(B[i][1+j], B[k][1+j]));
      if (i==k) acc.r += no;
      A[i][k] = acc;
    }

  // LU with partial pivoting (cabs1, bubble-swap keeps static indexing)
  #pragma unroll
  for (int k=0;k<4;k++){
    #pragma unroll
    for (int i=k+1;i<4;i++){
      float vk = fabsf(A[k][k].r)+fabsf(A[k][k].i);
      float vi = fabsf(A[i][k].r)+fabsf(A[i][k].i);
      if (vi > vk){
        #pragma unroll
        for (int j=0;j<4;j++){ cpx tmp=A[k][j]; A[k][j]=A[i][j]; A[i][j]=tmp; }
        #pragma unroll
        for (int j=0;j<5;j++){ cpx tmp=B[k][j]; B[k][j]=B[i][j]; B[i][j]=tmp; }
      }
    }
    #pragma unroll
    for (int i=k+1;i<4;i++){
      cpx l = cdiv(A[i][k], A[k][k]);
      #pragma unroll
      for (int j=k+1;j<4;j++) A[i][j] = csub(A[i][j], cmul(l, A[k][j]));
      #pragma unroll
      for (int j=0;j<5;j++) B[i][j] = csub(B[i][j], cmul(l, B[k][j]));
    }
  }
  #pragma unroll
  for (int k=3;k>=0;k--){
    #pragma unroll
    for (int j=0;j<5;j++){
      cpx s = B[k][j];
      #pragma unroll
      for (int m=k+1;m<4;m++) s = csub(s, cmul(A[k][m], B[m][j]));
      B[k][j] = cdiv(s, A[k][k]);
    }
  }

  int bb = r / NSYM, s = r - bb*NSYM;
  float Lout[16];
  #pragma unroll
  for (int j=0;j<4;j++){
    cpx hj[4];
    #pragma unroll
    for (int i=0;i<4;i++){
      float2 v = s_h[(i*4+j)*128+tid];
      hj[i].r = v.x; hj[i].i = v.y;
    }
    cpx xr; xr.r=0.f; xr.i=0.f;
    float dj = 0.f;
    #pragma unroll
    for (int i=0;i<4;i++) xr = cadd(xr, cmulc(B[i][0], hj[i]));
    #pragma unroll
    for (int i=0;i<4;i++){ cpx t = cmulc(B[i][1+j], hj[i]); dj += t.r; }
    float xhr = xr.r / dj, xhi = xr.i / dj;
    float nv = fmaxf(1.0f/dj - 1.0f, 1e-12f);
    float m0[4] = {-1e30f,-1e30f,-1e30f,-1e30f};
    float m1[4] = {-1e30f,-1e30f,-1e30f,-1e30f};
    #pragma unroll
    for (int p=0;p<16;p++){
      float2 pt = s_pts[p];
      float dr = xhr - pt.x;
      float di = xhi - pt.y;
      float am = sqrtf(dr*dr + di*di);
      float met = -(am*am)/nv;
      #pragma unroll
      for (int q=0;q<4;q++){
        if ((p >> (3-q)) & 1) m1[q] = fmaxf(m1[q], met);
        else                  m0[q] = fmaxf(m0[q], met);
      }
    }
    #pragma unroll
    for (int q=0;q<4;q++) Lout[4*q + j] = m0[q] - m1[q];
  }
  float4* dst = reinterpret_cast<float4*>(g_Lch + bb*(NC*NUE) + 16*s);
  const float4* src = reinterpret_cast<const float4*>(Lout);
  dst[0]=src[0]; dst[1]=src[1]; dst[2]=src[2]; dst[3]=src[3];
}

// ---------------- LDPC decoder ----------------
__device__ __forceinline__ float eps_clamp(float t){
  float m = fmaxf(fabsf(t), 1e-7f);
  return __int_as_float((__float_as_int(t) & 0x80000000) | __float_as_int(m));
}
__device__ __forceinline__ float2 v2c2(float2 mv){
  float2 arg = f2mul(mv, f2c(0.5f));
  float axx = fabsf(arg.x), axy = fabsf(arg.y);
  float2 xc;
  xc.x = fminf(fmaxf(arg.x,-7.90531110763549805f),7.90531110763549805f);
  xc.y = fminf(fmaxf(arg.y,-7.90531110763549805f),7.90531110763549805f);
  float2 x2 = f2mul(xc,xc);
  float2 p = f2c(-2.76076847742355e-16f);
  p = f2fma(p,x2,f2c(2.00018790482477e-13f));
  p = f2fma(p,x2,f2c(-8.60467152213735e-11f));
  p = f2fma(p,x2,f2c(5.12229709037114e-08f));
  p = f2fma(p,x2,f2c(1.48572235717979e-05f));
  p = f2fma(p,x2,f2c(6.37261928875436e-04f));
  p = f2fma(p,x2,f2c(4.89352455891786e-03f));
  p = f2mul(p,xc);
  float2 q = f2c(1.19825839466702e-06f);
  q = f2fma(q,x2,f2c(1.18534705686654e-04f));
  q = f2fma(q,x2,f2c(2.26843463243900e-03f));
  q = f2fma(q,x2,f2c(4.89352518554385e-03f));
  float2 t;
  t.x = p.x/q.x; t.y = p.y/q.y;
  t.x = (axx < 0.0004f) ? arg.x : t.x;
  t.y = (axy < 0.0004f) ? arg.y : t.y;
  t.x = eps_clamp(t.x);
  t.y = eps_clamp(t.y);
  return t;
}
__device__ __forceinline__ float c2v_msg(float prod, float t){
  float ra = prod / t;
  ra = fminf(fmaxf(ra, -0.999999f), 0.999999f);
  float at = 0.5f*(log1pf(ra) - log1pf(-ra));
  return 2.0f*at;
}

__global__ void __launch_bounds__(512) k_decode(float* __restrict__ out){
  __shared__ float4 s_msg[NSLOT];   // 40000 B, padded degree-sorted slots
  int bb = blockIdx.x, tid = threadIdx.x;
  const float4* Lg = reinterpret_cast<const float4*>(g_Lch + bb*(NC*NUE));

  float4 Lv, Lp;
  int p0=0, p1=0, p2=0, pid=0;
  int start=0, deg=0;
  bool act = (tid < 500);
  if (act){
    int v = tid;
    Lv = Lg[v];
    Lp = Lg[KC + v];
    p0 = g_pos[3*v]; p1 = g_pos[3*v+1]; p2 = g_pos[3*v+2];
    pid = g_pos[NINFO + v];
    uint32_t sd = g_sd[tid];          // degree-sorted rank -> uniform warp degree
    start = (int)(sd & 0xffffu); deg = (int)(sd >> 16);
  }
  for (int i=tid;i<NSLOT;i+=512) s_msg[i] = make_float4(0.f,0.f,0.f,0.f);
  __syncthreads();

  for (int it=0; it<5; it++){
    // ---- variable nodes (packed pairs xy / zw) ----
    if (act){
      float4 c0 = s_msg[p0], c1 = s_msg[p1], c2 = s_msg[p2];
      float2 c0a = make_float2(c0.x,c0.y), c0b = make_float2(c0.z,c0.w);
      float2 c1a = make_float2(c1.x,c1.y), c1b = make_float2(c1.z,c1.w);
      float2 c2a = make_float2(c2.x,c2.y), c2b = make_float2(c2.z,c2.w);
      float2 La  = make_float2(Lv.x,Lv.y), Lb = make_float2(Lv.z,Lv.w);
      float2 vta = f2add(f2add(f2add(La,c0a),c1a),c2a);
      float2 vtb = f2add(f2add(f2add(Lb,c0b),c1b),c2b);
      float2 n0a = v2c2(make_float2(vta.x-c0a.x, vta.y-c0a.y));
      float2 n0b = v2c2(make_float2(vtb.x-c0b.x, vtb.y-c0b.y));
      float2 n1a = v2c2(make_float2(vta.x-c1a.x, vta.y-c1a.y));
      float2 n1b = v2c2(make_float2(vtb.x-c1b.x, vtb.y-c1b.y));
      float2 n2a = v2c2(make_float2(vta.x-c2a.x, vta.y-c2a.y));
      float2 n2b = v2c2(make_float2(vtb.x-c2b.x, vtb.y-c2b.y));
      s_msg[p0] = make_float4(n0a.x,n0a.y,n0b.x,n0b.y);
      s_msg[p1] = make_float4(n1a.x,n1a.y,n1b.x,n1b.y);
      s_msg[p2] = make_float4(n2a.x,n2a.y,n2b.x,n2b.y);
      float4 cp = s_msg[pid];
      float2 cpa = make_float2(cp.x,cp.y), cpb = make_float2(cp.z,cp.w);
      float2 Lpa = make_float2(Lp.x,Lp.y), Lpb = make_float2(Lp.z,Lp.w);
      float2 ta = f2add(Lpa,cpa);
      float2 tb = f2add(Lpb,cpb);
      float2 npa = v2c2(make_float2(ta.x-cpa.x, ta.y-cpa.y));
      float2 npb = v2c2(make_float2(tb.x-cpb.x, tb.y-cpb.y));
      s_msg[pid] = make_float4(npa.x,npa.y,npb.x,npb.y);
    }
    __syncthreads();
    // ---- check nodes (uniform degree per warp; odd slot stride) ----
    if (act){
      int st = start, dg = deg;
      float2 pa = f2c(1.f), pb = f2c(1.f);
      for (int d=0; d<dg; d++){
        float4 t = s_msg[st+d];
        pa = f2mul(pa, make_float2(t.x,t.y));
        pb = f2mul(pb, make_float2(t.z,t.w));
      }
      for (int d=0; d<dg; d++){
        float4 t = s_msg[st+d];
        float4 o;
        o.x = c2v_msg(pa.x, t.x);
        o.y = c2v_msg(pa.y, t.y);
        o.z = c2v_msg(pb.x, t.z);
        o.w = c2v_msg(pb.y, t.w);
        s_msg[st+d] = o;
      }
    }
    __syncthreads();
  }

  float* bh = out + COLS*KC;
  if (act){
    int v = tid;
    float4 c0 = s_msg[p0], c1 = s_msg[p1], c2 = s_msg[p2];
    float vx = ((Lv.x + c0.x) + c1.x) + c2.x;
    float vy = ((Lv.y + c0.y) + c1.y) + c2.y;
    float vz = ((Lv.z + c0.z) + c1.z) + c2.z;
    float vw = ((Lv.w + c0.w) + c1.w) + c2.w;
    bh[(bb*4+0)*KC + v] = (vx < 0.f) ? 1.0f : 0.0f;
    bh[(bb*4+1)*KC + v] = (vy < 0.f) ? 1.0f : 0.0f;
    bh[(bb*4+2)*KC + v] = (vz < 0.f) ? 1.0f : 0.0f;
    bh[(bb*4+3)*KC + v] = (vw < 0.f) ? 1.0f : 0.0f;
  }
}

// ---------------- entry ----------------
extern "C" void kernel_launch(void* const* d_in, const int* in_sizes, int n_in,
                              void* d_out, int out_size)
{
  (void)in_sizes; (void)out_size;
  int off = (n_in >= 10) ? 1 : 0;
  const float* ebno = (const float*)d_in[off+0];
  const int*   b    = (const int*)  d_in[off+1];
  const int*   cn   = (const int*)  d_in[off+3];
  const float* hre  = (const float*)d_in[off+5];
  const float* him  = (const float*)d_in[off+6];
  const float* nre  = (const float*)d_in[off+7];
  const float* nim  = (const float*)d_in[off+8];
  float* out = (float*)d_out;

  k_setup<<<1, 512>>>(cn, ebno);
  k_encode<<<NGRP, 256>>>(b, out);
  k_lmmse<<<(NROW + 127)/128, 128>>>(hre, him, nre, nim);
  k_decode<<<BATCH, 512>>>(out);
}